// round 11
// baseline (speedup 1.0000x reference)
#include <cuda_runtime.h>
#include <cstdint>

// 2-layer LSTM (B=4096,T=256,D=4,H=64)+FC, fp32.
// R10: K-split 8gx8e tile. 256 thr/CTA (2 warps/SMSP): set A = K-chunks
// 0..15, set B = 16..31; partial accs exchanged via smem ([part][tid],
// conflict-free), update split by unit (A: unit0, B: unit1). Same pipelined
// GEMM inner loop as R9 (w slot prefetched one ahead, p/q reg sets).

#define TT 256
#define V_OFF 131072
#define VBUF  16384
#define P_OFF 163840          // 32KB partial-exchange scratch
#define SM_TOTAL 196608

typedef unsigned long long u64;
__device__ float g_h1[(size_t)128 * TT * 2048];   // [blk][t][j64][e32]

static __device__ __forceinline__ u64 pkss(float f){u64 r;asm("mov.b64 %0,{%1,%1};":"=l"(r):"f"(f));return r;}
static __device__ __forceinline__ void up2(u64 v,float&a,float&b){asm("mov.b64 {%0,%1},%2;":"=f"(a),"=f"(b):"l"(v));}
static __device__ __forceinline__ u64 f2(u64 a,u64 b,u64 c){u64 d;asm("fma.rn.f32x2 %0,%1,%2,%3;":"=l"(d):"l"(a),"l"(b),"l"(c));return d;}
static __device__ __forceinline__ u64 a2(u64 a,u64 b){u64 d;asm("add.rn.f32x2 %0,%1,%2;":"=l"(d):"l"(a),"l"(b));return d;}
static __device__ __forceinline__ float tanha(float x){float r;asm("tanh.approx.f32 %0,%1;":"=f"(r):"f"(x));return r;}
static __device__ __forceinline__ float sigt(float x){return fmaf(0.5f,tanha(0.5f*x),0.5f);}
static __device__ __forceinline__ uint32_t s2u(const void*p){uint32_t a;
    asm("{.reg .u64 t;cvta.to.shared.u64 t,%1;cvt.u32.u64 %0,t;}":"=r"(a):"l"(p));return a;}

#define XL2(d0,d1,IMM) asm volatile("ld.shared.v2.u64 {%0,%1},[%2+%3];" \
    :"=l"(d0),"=l"(d1):"r"(xb),"n"(IMM))
#define STS4(A,IMM,V) asm volatile("st.shared.v4.f32 [%0+%1],{%2,%3,%4,%5};" \
    ::"r"(A),"n"(IMM),"f"((V).x),"f"((V).y),"f"((V).z),"f"((V).w))
#define STS1(A,IMM,V) asm volatile("st.shared.f32 [%0+%1],%2;"::"r"(A),"n"(IMM),"f"(V))
#define WLOADP(IMM) asm volatile("ld.shared.v4.f32 {%0,%1,%2,%3},[%4+%5];" \
    :"=f"(p0),"=f"(p1),"=f"(p2),"=f"(p3):"r"(wb),"n"(IMM))
#define WLOADQ(IMM) asm volatile("ld.shared.v4.f32 {%0,%1,%2,%3},[%4+%5];" \
    :"=f"(q0),"=f"(q1),"=f"(q2),"=f"(q3):"r"(wb),"n"(IMM))

#define SLOTF(S,W) do{ u64 ws; \
  ws=pkss(W##0);acc[S][0]=f2(ws,x00,acc[S][0]);acc[S][1]=f2(ws,x01,acc[S][1]); \
               acc[S][2]=f2(ws,x02,acc[S][2]);acc[S][3]=f2(ws,x03,acc[S][3]); \
  ws=pkss(W##1);acc[S][0]=f2(ws,x10,acc[S][0]);acc[S][1]=f2(ws,x11,acc[S][1]); \
               acc[S][2]=f2(ws,x12,acc[S][2]);acc[S][3]=f2(ws,x13,acc[S][3]); \
  ws=pkss(W##2);acc[S][0]=f2(ws,x20,acc[S][0]);acc[S][1]=f2(ws,x21,acc[S][1]); \
               acc[S][2]=f2(ws,x22,acc[S][2]);acc[S][3]=f2(ws,x23,acc[S][3]); \
  ws=pkss(W##3);acc[S][0]=f2(ws,x30,acc[S][0]);acc[S][1]=f2(ws,x31,acc[S][1]); \
               acc[S][2]=f2(ws,x32,acc[S][2]);acc[S][3]=f2(ws,x33,acc[S][3]); \
}while(0)

#define PCHUNK do{ \
  u64 x00,x01,x02,x03,x10,x11,x12,x13,x20,x21,x22,x23,x30,x31,x32,x33; \
  XL2(x00,x01,0);  XL2(x02,x03,16); XL2(x10,x11,128);XL2(x12,x13,144); \
  XL2(x20,x21,256);XL2(x22,x23,272);XL2(x30,x31,384);XL2(x32,x33,400); \
  WLOADQ(512);  SLOTF(0,p); \
  WLOADP(1024); SLOTF(1,q); \
  WLOADQ(1536); SLOTF(2,p); \
  WLOADP(2048); SLOTF(3,q); \
  WLOADQ(2560); SLOTF(4,p); \
  WLOADP(3072); SLOTF(5,q); \
  WLOADQ(3584); SLOTF(6,p); \
  WLOADP(4096); SLOTF(7,q); \
  wb+=4096; xb+=512; \
}while(0)

// store my other-unit partials (slots SB..SB+3) to [part16][tid]*16B scratch
#define PST(SB,A_) do{ \
  asm volatile("st.shared.v2.u64 [%0+0],{%1,%2};"::"r"(A_),"l"(acc[SB][0]),"l"(acc[SB][1])); \
  asm volatile("st.shared.v2.u64 [%0+2048],{%1,%2};"::"r"(A_),"l"(acc[SB][2]),"l"(acc[SB][3])); \
  asm volatile("st.shared.v2.u64 [%0+4096],{%1,%2};"::"r"(A_),"l"(acc[(SB)+1][0]),"l"(acc[(SB)+1][1])); \
  asm volatile("st.shared.v2.u64 [%0+6144],{%1,%2};"::"r"(A_),"l"(acc[(SB)+1][2]),"l"(acc[(SB)+1][3])); \
  asm volatile("st.shared.v2.u64 [%0+8192],{%1,%2};"::"r"(A_),"l"(acc[(SB)+2][0]),"l"(acc[(SB)+2][1])); \
  asm volatile("st.shared.v2.u64 [%0+10240],{%1,%2};"::"r"(A_),"l"(acc[(SB)+2][2]),"l"(acc[(SB)+2][3])); \
  asm volatile("st.shared.v2.u64 [%0+12288],{%1,%2};"::"r"(A_),"l"(acc[(SB)+3][0]),"l"(acc[(SB)+3][1])); \
  asm volatile("st.shared.v2.u64 [%0+14336],{%1,%2};"::"r"(A_),"l"(acc[(SB)+3][2]),"l"(acc[(SB)+3][3])); \
}while(0)
// load peer's partials for my unit (slots SB..SB+3) and add
#define PLA(SB,A_) do{ u64 t0,t1; \
  asm volatile("ld.shared.v2.u64 {%0,%1},[%2+0];":"=l"(t0),"=l"(t1):"r"(A_)); \
  acc[SB][0]=a2(acc[SB][0],t0); acc[SB][1]=a2(acc[SB][1],t1); \
  asm volatile("ld.shared.v2.u64 {%0,%1},[%2+2048];":"=l"(t0),"=l"(t1):"r"(A_)); \
  acc[SB][2]=a2(acc[SB][2],t0); acc[SB][3]=a2(acc[SB][3],t1); \
  asm volatile("ld.shared.v2.u64 {%0,%1},[%2+4096];":"=l"(t0),"=l"(t1):"r"(A_)); \
  acc[(SB)+1][0]=a2(acc[(SB)+1][0],t0); acc[(SB)+1][1]=a2(acc[(SB)+1][1],t1); \
  asm volatile("ld.shared.v2.u64 {%0,%1},[%2+6144];":"=l"(t0),"=l"(t1):"r"(A_)); \
  acc[(SB)+1][2]=a2(acc[(SB)+1][2],t0); acc[(SB)+1][3]=a2(acc[(SB)+1][3],t1); \
  asm volatile("ld.shared.v2.u64 {%0,%1},[%2+8192];":"=l"(t0),"=l"(t1):"r"(A_)); \
  acc[(SB)+2][0]=a2(acc[(SB)+2][0],t0); acc[(SB)+2][1]=a2(acc[(SB)+2][1],t1); \
  asm volatile("ld.shared.v2.u64 {%0,%1},[%2+10240];":"=l"(t0),"=l"(t1):"r"(A_)); \
  acc[(SB)+2][2]=a2(acc[(SB)+2][2],t0); acc[(SB)+2][3]=a2(acc[(SB)+2][3],t1); \
  asm volatile("ld.shared.v2.u64 {%0,%1},[%2+12288];":"=l"(t0),"=l"(t1):"r"(A_)); \
  acc[(SB)+3][0]=a2(acc[(SB)+3][0],t0); acc[(SB)+3][1]=a2(acc[(SB)+3][1],t1); \
  asm volatile("ld.shared.v2.u64 {%0,%1},[%2+14336];":"=l"(t0),"=l"(t1):"r"(A_)); \
  acc[(SB)+3][2]=a2(acc[(SB)+3][2],t0); acc[(SB)+3][3]=a2(acc[(SB)+3][3],t1); \
}while(0)

// update ONE unit (slots SB..SB+3) -> cc[8], hv[8]
#define UPD8(SB) do{ _Pragma("unroll") for(int p_=0;p_<4;p_++){ \
  float i0,i1,f0,f1,g0,g1,o0,o1; \
  up2(acc[SB][p_],i0,i1);      up2(acc[(SB)+1][p_],f0,f1); \
  up2(acc[(SB)+2][p_],g0,g1);  up2(acc[(SB)+3][p_],o0,o1); \
  cc[2*p_]  =sigt(f0)*cc[2*p_]  +sigt(i0)*tanha(g0); \
  cc[2*p_+1]=sigt(f1)*cc[2*p_+1]+sigt(i1)*tanha(g1); \
  hv[2*p_]  =sigt(o0)*tanha(cc[2*p_]); \
  hv[2*p_+1]=sigt(o1)*tanha(cc[2*p_+1]); }}while(0)

#define EXCHANGE_AND_UPDATE() do{ \
  if(st==0){ PST(4,pst_a); } else { PST(0,pst_a); } \
}while(0)

// ---------------------------------------------------------------------------
__global__ void __launch_bounds__(256,1) lstm_l1(
    const float* __restrict__ Wih,const float* __restrict__ Whh,
    const float* __restrict__ bih,const float* __restrict__ bhh,
    const float* __restrict__ Wfc,const float* __restrict__ bfc,
    float* __restrict__ out)
{
    extern __shared__ char sm[];
    const int tid=threadIdx.x, st=tid>>7, t=tid&127, eg=t&3, gg=t>>2;
    const int b0=blockIdx.x*32;

    for(int idx=tid;idx<8192;idx+=256){            // weights [kc32][s8][gg32]
        int kc=idx>>8,s=(idx>>5)&7,g=idx&31;
        int r=(s&3)*64+2*g+(s>>2), k=kc*4;
        const float* src = (k<64)? Wih+r*64+k : Whh+r*64+(k-64);
        *(float4*)(sm+kc*4096+s*512+g*16)=*(const float4*)src;
    }

    const uint32_t smb=s2u(sm);
    const uint32_t wb0=smb+gg*16+st*65536;          // set B: chunks 16..31
    uint32_t xrd=smb+V_OFF+eg*32+st*8192;           // set B: v rows 64..127
    uint32_t hs=smb+V_OFF+VBUF+(64+2*gg+st)*128+eg*32;
    uint32_t ps=smb+V_OFF+VBUF+(2*gg+st)*128+eg*32;
    const uint32_t pst_a=smb+P_OFF+st*16384+t*16;
    const uint32_t pld_a=smb+P_OFF+(1-st)*16384+t*16;

    const float* h1p=g_h1+(size_t)blockIdx.x*TT*2048+(2*gg+st)*32+eg*8;
    {   // V0: row (2gg+st) <- h1[t=0]; row (64+2gg+st) <- 0
        float4 a=*(const float4*)h1p, b4=*(const float4*)(h1p+4);
        uint32_t vi=smb+V_OFF+(2*gg+st)*128+eg*32;
        STS4(vi,0,a); STS4(vi,16,b4);
        float4 z=make_float4(0.f,0.f,0.f,0.f);
        STS4(vi,8192,z); STS4(vi,8208,z);
    }
    h1p+=2048;

    float bias[8];
#pragma unroll
    for(int s=0;s<8;s++){
        int r=(s&3)*64+2*gg+(s>>2);
        bias[s]=(st==0)? (bih[r]+bhh[r]) : 0.f;
    }
    float cc[8], hv[8];
#pragma unroll
    for(int e=0;e<8;e++)cc[e]=0.f;
    int xf=VBUF,hf=-VBUF;
    __syncthreads();

    for(int s=0;s<TT;s++){
        float4 pA,pB;
        if(s+1<TT){pA=*(const float4*)h1p; pB=*(const float4*)(h1p+4);}
        else {pA=pB=make_float4(0.f,0.f,0.f,0.f);}
        h1p+=2048;

        u64 acc[8][4];
#pragma unroll
        for(int q=0;q<8;q++){u64 bp=pkss(bias[q]);
            acc[q][0]=bp;acc[q][1]=bp;acc[q][2]=bp;acc[q][3]=bp;}

        float p0,p1,p2,p3,q0,q1,q2,q3;
        uint32_t xb=xrd, wb=wb0;
        WLOADP(0);
#pragma unroll 4
        for(int kc=0;kc<16;kc++) PCHUNK;

        if(st==0){ PST(4,pst_a); } else { PST(0,pst_a); }
        STS4(ps,0,pA); STS4(ps,16,pB);
        __syncthreads();                            // partials visible
        if(st==0){ PLA(0,pld_a); UPD8(0); }
        else     { PLA(4,pld_a); UPD8(4); }
        {
            float4 h4=make_float4(hv[0],hv[1],hv[2],hv[3]);
            float4 h5=make_float4(hv[4],hv[5],hv[6],hv[7]);
            STS4(hs,0,h4); STS4(hs,16,h5);
        }
        __syncthreads();                            // v[next] complete
        xrd+=xf;xf=-xf; hs+=hf;ps+=hf;hf=-hf;
    }

    // fused FC: thread owns unit j=2gg+st
    {
        float wf=Wfc[2*gg+st];
        float4 t0=make_float4(hv[0]*wf,hv[1]*wf,hv[2]*wf,hv[3]*wf);
        float4 t1=make_float4(hv[4]*wf,hv[5]*wf,hv[6]*wf,hv[7]*wf);
        uint32_t pb=smb+V_OFF+(2*gg+st)*128+eg*32;
        STS4(pb,0,t0); STS4(pb,16,t1);
        __syncthreads();
        if(tid<32){
            float v=bfc[0];
#pragma unroll
            for(int g=0;g<64;g++) v+=*(const float*)(sm+V_OFF+g*128+tid*4);
            out[b0+tid]=v;
        }
    }
}

// ---------------------------------------------------------------------------
// Layer 0: v rows 0..3 = x (chunk 0), rows 4..67 = h (chunks 1..16).
// Set A: chunks 0..8 (9), set B: chunks 9..16 (8).
__global__ void __launch_bounds__(256,1) lstm_l0(
    const float* __restrict__ x,const float* __restrict__ Wih,
    const float* __restrict__ Whh,const float* __restrict__ bih,
    const float* __restrict__ bhh)
{
    extern __shared__ char sm[];
    const int tid=threadIdx.x, st=tid>>7, t=tid&127, eg=t&3, gg=t>>2;
    const int b0=blockIdx.x*32;

    for(int idx=tid;idx<4352;idx+=256){            // weights [kc17][s8][gg32]
        int kc=idx>>8,s=(idx>>5)&7,g=idx&31;
        int r=(s&3)*64+2*g+(s>>2);
        const float* src = (kc==0)? Wih+r*4 : Whh+r*64+(kc-1)*4;
        *(float4*)(sm+kc*4096+s*512+g*16)=*(const float4*)src;
    }

    const uint32_t smb=s2u(sm);
    const uint32_t wb0=smb+gg*16+st*36864;          // set B starts chunk 9
    uint32_t xrd=smb+V_OFF+eg*32+st*4608;           // set B rows 36..67
    uint32_t hs=smb+V_OFF+VBUF+(4+2*gg+st)*128+eg*32;
    uint32_t xs=smb+V_OFF+VBUF+(tid&127)*4;         // only tid<32 uses
    const uint32_t pst_a=smb+P_OFF+st*16384+t*16;
    const uint32_t pld_a=smb+P_OFF+(1-st)*16384+t*16;
    const int nch = 9 - st;

    {   // V0: h row (4+2gg+st) <- 0
        float4 z=make_float4(0.f,0.f,0.f,0.f);
        uint32_t vi=smb+V_OFF+(4+2*gg+st)*128+eg*32;
        STS4(vi,0,z); STS4(vi,16,z);
    }
    const float* xp=0;
    if(tid<32){
        xp=x+(size_t)(b0+tid)*TT*4;
        float4 x0=*(const float4*)xp;
        uint32_t xi=smb+V_OFF+tid*4;
        STS1(xi,0,x0.x);STS1(xi,128,x0.y);STS1(xi,256,x0.z);STS1(xi,384,x0.w);
    }
    float* gp=g_h1+(size_t)blockIdx.x*TT*2048+(2*gg+st)*32+eg*8;

    float bias[8];
#pragma unroll
    for(int s=0;s<8;s++){
        int r=(s&3)*64+2*gg+(s>>2);
        bias[s]=(st==0)? (bih[r]+bhh[r]) : 0.f;
    }
    float cc[8], hv[8];
#pragma unroll
    for(int e=0;e<8;e++)cc[e]=0.f;
    int xf=VBUF,hf=-VBUF;
    __syncthreads();

    for(int s=0;s<TT;s++){
        float4 px=make_float4(0.f,0.f,0.f,0.f);
        if(tid<32&&s+1<TT)px=*(const float4*)(xp+(size_t)(s+1)*4);

        u64 acc[8][4];
#pragma unroll
        for(int q=0;q<8;q++){u64 bp=pkss(bias[q]);
            acc[q][0]=bp;acc[q][1]=bp;acc[q][2]=bp;acc[q][3]=bp;}

        float p0,p1,p2,p3,q0,q1,q2,q3;
        uint32_t xb=xrd, wb=wb0;
        WLOADP(0);
#pragma unroll 3
        for(int kc=0;kc<nch;kc++) PCHUNK;

        if(st==0){ PST(4,pst_a); } else { PST(0,pst_a); }
        if(tid<32){STS1(xs,0,px.x);STS1(xs,128,px.y);STS1(xs,256,px.z);STS1(xs,384,px.w);}
        __syncthreads();
        if(st==0){ PLA(0,pld_a); UPD8(0); }
        else     { PLA(4,pld_a); UPD8(4); }
        {
            float4 h4=make_float4(hv[0],hv[1],hv[2],hv[3]);
            float4 h5=make_float4(hv[4],hv[5],hv[6],hv[7]);
            STS4(hs,0,h4); STS4(hs,16,h5);
            *(float4*)(gp)  =h4;
            *(float4*)(gp+4)=h5;
        }
        gp+=2048;
        __syncthreads();
        xrd+=xf;xf=-xf; hs+=hf;xs+=hf;hf=-hf;
    }
}

// ---------------------------------------------------------------------------
extern "C" void kernel_launch(void* const* d_in, const int* in_sizes, int n_in,
                              void* d_out, int out_size)
{
    const float* x    =(const float*)d_in[0];
    const float* Wih0 =(const float*)d_in[1];
    const float* Whh0 =(const float*)d_in[2];
    const float* bih0 =(const float*)d_in[3];
    const float* bhh0 =(const float*)d_in[4];
    const float* Wih1 =(const float*)d_in[5];
    const float* Whh1 =(const float*)d_in[6];
    const float* bih1 =(const float*)d_in[7];
    const float* bhh1 =(const float*)d_in[8];
    const float* Wfc  =(const float*)d_in[9];
    const float* bfc  =(const float*)d_in[10];
    float* out=(float*)d_out;

    cudaFuncSetAttribute(lstm_l0,cudaFuncAttributeMaxDynamicSharedMemorySize,SM_TOTAL);
    cudaFuncSetAttribute(lstm_l1,cudaFuncAttributeMaxDynamicSharedMemorySize,SM_TOTAL);
    lstm_l0<<<128,256,SM_TOTAL>>>(x,Wih0,Whh0,bih0,bhh0);
    lstm_l1<<<128,256,SM_TOTAL>>>(Wih1,Whh1,bih1,bhh1,Wfc,bfc,out);
}

// round 12
// speedup vs baseline: 1.0581x; 1.0581x over previous
#include <cuda_runtime.h>
#include <cstdint>

// 2-layer LSTM (B=4096,T=256,D=4,H=64)+FC, fp32.
// R10: K-split 8gx8e tile. 256 thr/CTA (2 warps/SMSP): set A = K-chunks
// 0..15, set B = 16..31; partial accs exchanged via smem ([part][tid],
// conflict-free), update split by unit (A: unit0, B: unit1). Same pipelined
// GEMM inner loop as R9 (w slot prefetched one ahead, p/q reg sets).

#define TT 256
#define V_OFF 131072
#define VBUF  16384
#define P_OFF 163840          // 32KB partial-exchange scratch
#define SM_TOTAL 196608

typedef unsigned long long u64;
__device__ float g_h1[(size_t)128 * TT * 2048];   // [blk][t][j64][e32]

static __device__ __forceinline__ u64 pkss(float f){u64 r;asm("mov.b64 %0,{%1,%1};":"=l"(r):"f"(f));return r;}
static __device__ __forceinline__ void up2(u64 v,float&a,float&b){asm("mov.b64 {%0,%1},%2;":"=f"(a),"=f"(b):"l"(v));}
static __device__ __forceinline__ u64 f2(u64 a,u64 b,u64 c){u64 d;asm("fma.rn.f32x2 %0,%1,%2,%3;":"=l"(d):"l"(a),"l"(b),"l"(c));return d;}
static __device__ __forceinline__ u64 a2(u64 a,u64 b){u64 d;asm("add.rn.f32x2 %0,%1,%2;":"=l"(d):"l"(a),"l"(b));return d;}
static __device__ __forceinline__ float tanha(float x){float r;asm("tanh.approx.f32 %0,%1;":"=f"(r):"f"(x));return r;}
static __device__ __forceinline__ float sigt(float x){return fmaf(0.5f,tanha(0.5f*x),0.5f);}
static __device__ __forceinline__ uint32_t s2u(const void*p){uint32_t a;
    asm("{.reg .u64 t;cvta.to.shared.u64 t,%1;cvt.u32.u64 %0,t;}":"=r"(a):"l"(p));return a;}

#define XL2(d0,d1,IMM) asm volatile("ld.shared.v2.u64 {%0,%1},[%2+%3];" \
    :"=l"(d0),"=l"(d1):"r"(xb),"n"(IMM))
#define STS4(A,IMM,V) asm volatile("st.shared.v4.f32 [%0+%1],{%2,%3,%4,%5};" \
    ::"r"(A),"n"(IMM),"f"((V).x),"f"((V).y),"f"((V).z),"f"((V).w))
#define STS1(A,IMM,V) asm volatile("st.shared.f32 [%0+%1],%2;"::"r"(A),"n"(IMM),"f"(V))
#define WLOADP(IMM) asm volatile("ld.shared.v4.f32 {%0,%1,%2,%3},[%4+%5];" \
    :"=f"(p0),"=f"(p1),"=f"(p2),"=f"(p3):"r"(wb),"n"(IMM))
#define WLOADQ(IMM) asm volatile("ld.shared.v4.f32 {%0,%1,%2,%3},[%4+%5];" \
    :"=f"(q0),"=f"(q1),"=f"(q2),"=f"(q3):"r"(wb),"n"(IMM))

#define SLOTF(S,W) do{ u64 ws; \
  ws=pkss(W##0);acc[S][0]=f2(ws,x00,acc[S][0]);acc[S][1]=f2(ws,x01,acc[S][1]); \
               acc[S][2]=f2(ws,x02,acc[S][2]);acc[S][3]=f2(ws,x03,acc[S][3]); \
  ws=pkss(W##1);acc[S][0]=f2(ws,x10,acc[S][0]);acc[S][1]=f2(ws,x11,acc[S][1]); \
               acc[S][2]=f2(ws,x12,acc[S][2]);acc[S][3]=f2(ws,x13,acc[S][3]); \
  ws=pkss(W##2);acc[S][0]=f2(ws,x20,acc[S][0]);acc[S][1]=f2(ws,x21,acc[S][1]); \
               acc[S][2]=f2(ws,x22,acc[S][2]);acc[S][3]=f2(ws,x23,acc[S][3]); \
  ws=pkss(W##3);acc[S][0]=f2(ws,x30,acc[S][0]);acc[S][1]=f2(ws,x31,acc[S][1]); \
               acc[S][2]=f2(ws,x32,acc[S][2]);acc[S][3]=f2(ws,x33,acc[S][3]); \
}while(0)

#define PCHUNK do{ \
  u64 x00,x01,x02,x03,x10,x11,x12,x13,x20,x21,x22,x23,x30,x31,x32,x33; \
  XL2(x00,x01,0);  XL2(x02,x03,16); XL2(x10,x11,128);XL2(x12,x13,144); \
  XL2(x20,x21,256);XL2(x22,x23,272);XL2(x30,x31,384);XL2(x32,x33,400); \
  WLOADQ(512);  SLOTF(0,p); \
  WLOADP(1024); SLOTF(1,q); \
  WLOADQ(1536); SLOTF(2,p); \
  WLOADP(2048); SLOTF(3,q); \
  WLOADQ(2560); SLOTF(4,p); \
  WLOADP(3072); SLOTF(5,q); \
  WLOADQ(3584); SLOTF(6,p); \
  WLOADP(4096); SLOTF(7,q); \
  wb+=4096; xb+=512; \
}while(0)

// store my other-unit partials (slots SB..SB+3) to [part16][tid]*16B scratch
#define PST(SB,A_) do{ \
  asm volatile("st.shared.v2.u64 [%0+0],{%1,%2};"::"r"(A_),"l"(acc[SB][0]),"l"(acc[SB][1])); \
  asm volatile("st.shared.v2.u64 [%0+2048],{%1,%2};"::"r"(A_),"l"(acc[SB][2]),"l"(acc[SB][3])); \
  asm volatile("st.shared.v2.u64 [%0+4096],{%1,%2};"::"r"(A_),"l"(acc[(SB)+1][0]),"l"(acc[(SB)+1][1])); \
  asm volatile("st.shared.v2.u64 [%0+6144],{%1,%2};"::"r"(A_),"l"(acc[(SB)+1][2]),"l"(acc[(SB)+1][3])); \
  asm volatile("st.shared.v2.u64 [%0+8192],{%1,%2};"::"r"(A_),"l"(acc[(SB)+2][0]),"l"(acc[(SB)+2][1])); \
  asm volatile("st.shared.v2.u64 [%0+10240],{%1,%2};"::"r"(A_),"l"(acc[(SB)+2][2]),"l"(acc[(SB)+2][3])); \
  asm volatile("st.shared.v2.u64 [%0+12288],{%1,%2};"::"r"(A_),"l"(acc[(SB)+3][0]),"l"(acc[(SB)+3][1])); \
  asm volatile("st.shared.v2.u64 [%0+14336],{%1,%2};"::"r"(A_),"l"(acc[(SB)+3][2]),"l"(acc[(SB)+3][3])); \
}while(0)
// load peer's partials for my unit (slots SB..SB+3) and add
#define PLA(SB,A_) do{ u64 t0,t1; \
  asm volatile("ld.shared.v2.u64 {%0,%1},[%2+0];":"=l"(t0),"=l"(t1):"r"(A_)); \
  acc[SB][0]=a2(acc[SB][0],t0); acc[SB][1]=a2(acc[SB][1],t1); \
  asm volatile("ld.shared.v2.u64 {%0,%1},[%2+2048];":"=l"(t0),"=l"(t1):"r"(A_)); \
  acc[SB][2]=a2(acc[SB][2],t0); acc[SB][3]=a2(acc[SB][3],t1); \
  asm volatile("ld.shared.v2.u64 {%0,%1},[%2+4096];":"=l"(t0),"=l"(t1):"r"(A_)); \
  acc[(SB)+1][0]=a2(acc[(SB)+1][0],t0); acc[(SB)+1][1]=a2(acc[(SB)+1][1],t1); \
  asm volatile("ld.shared.v2.u64 {%0,%1},[%2+6144];":"=l"(t0),"=l"(t1):"r"(A_)); \
  acc[(SB)+1][2]=a2(acc[(SB)+1][2],t0); acc[(SB)+1][3]=a2(acc[(SB)+1][3],t1); \
  asm volatile("ld.shared.v2.u64 {%0,%1},[%2+8192];":"=l"(t0),"=l"(t1):"r"(A_)); \
  acc[(SB)+2][0]=a2(acc[(SB)+2][0],t0); acc[(SB)+2][1]=a2(acc[(SB)+2][1],t1); \
  asm volatile("ld.shared.v2.u64 {%0,%1},[%2+10240];":"=l"(t0),"=l"(t1):"r"(A_)); \
  acc[(SB)+2][2]=a2(acc[(SB)+2][2],t0); acc[(SB)+2][3]=a2(acc[(SB)+2][3],t1); \
  asm volatile("ld.shared.v2.u64 {%0,%1},[%2+12288];":"=l"(t0),"=l"(t1):"r"(A_)); \
  acc[(SB)+3][0]=a2(acc[(SB)+3][0],t0); acc[(SB)+3][1]=a2(acc[(SB)+3][1],t1); \
  asm volatile("ld.shared.v2.u64 {%0,%1},[%2+14336];":"=l"(t0),"=l"(t1):"r"(A_)); \
  acc[(SB)+3][2]=a2(acc[(SB)+3][2],t0); acc[(SB)+3][3]=a2(acc[(SB)+3][3],t1); \
}while(0)

// update ONE unit (slots SB..SB+3) -> cc[8], hv[8]
#define UPD8(SB) do{ _Pragma("unroll") for(int p_=0;p_<4;p_++){ \
  float i0,i1,f0,f1,g0,g1,o0,o1; \
  up2(acc[SB][p_],i0,i1);      up2(acc[(SB)+1][p_],f0,f1); \
  up2(acc[(SB)+2][p_],g0,g1);  up2(acc[(SB)+3][p_],o0,o1); \
  cc[2*p_]  =sigt(f0)*cc[2*p_]  +sigt(i0)*tanha(g0); \
  cc[2*p_+1]=sigt(f1)*cc[2*p_+1]+sigt(i1)*tanha(g1); \
  hv[2*p_]  =sigt(o0)*tanha(cc[2*p_]); \
  hv[2*p_+1]=sigt(o1)*tanha(cc[2*p_+1]); }}while(0)

#define EXCHANGE_AND_UPDATE() do{ \
  if(st==0){ PST(4,pst_a); } else { PST(0,pst_a); } \
}while(0)

// ---------------------------------------------------------------------------
__global__ void __launch_bounds__(256,1) lstm_l1(
    const float* __restrict__ Wih,const float* __restrict__ Whh,
    const float* __restrict__ bih,const float* __restrict__ bhh,
    const float* __restrict__ Wfc,const float* __restrict__ bfc,
    float* __restrict__ out)
{
    extern __shared__ char sm[];
    const int tid=threadIdx.x, st=tid>>7, t=tid&127, eg=t&3, gg=t>>2;
    const int b0=blockIdx.x*32;

    for(int idx=tid;idx<8192;idx+=256){            // weights [kc32][s8][gg32]
        int kc=idx>>8,s=(idx>>5)&7,g=idx&31;
        int r=(s&3)*64+2*g+(s>>2), k=kc*4;
        const float* src = (k<64)? Wih+r*64+k : Whh+r*64+(k-64);
        *(float4*)(sm+kc*4096+s*512+g*16)=*(const float4*)src;
    }

    const uint32_t smb=s2u(sm);
    const uint32_t wb0=smb+gg*16+st*65536;          // set B: chunks 16..31
    uint32_t xrd=smb+V_OFF+eg*32+st*8192;           // set B: v rows 64..127
    uint32_t hs=smb+V_OFF+VBUF+(64+2*gg+st)*128+eg*32;
    uint32_t ps=smb+V_OFF+VBUF+(2*gg+st)*128+eg*32;
    const uint32_t pst_a=smb+P_OFF+st*16384+t*16;
    const uint32_t pld_a=smb+P_OFF+(1-st)*16384+t*16;

    const float* h1p=g_h1+(size_t)blockIdx.x*TT*2048+(2*gg+st)*32+eg*8;
    {   // V0: row (2gg+st) <- h1[t=0]; row (64+2gg+st) <- 0
        float4 a=*(const float4*)h1p, b4=*(const float4*)(h1p+4);
        uint32_t vi=smb+V_OFF+(2*gg+st)*128+eg*32;
        STS4(vi,0,a); STS4(vi,16,b4);
        float4 z=make_float4(0.f,0.f,0.f,0.f);
        STS4(vi,8192,z); STS4(vi,8208,z);
    }
    h1p+=2048;

    float bias[8];
#pragma unroll
    for(int s=0;s<8;s++){
        int r=(s&3)*64+2*gg+(s>>2);
        bias[s]=(st==0)? (bih[r]+bhh[r]) : 0.f;
    }
    float cc[8], hv[8];
#pragma unroll
    for(int e=0;e<8;e++)cc[e]=0.f;
    int xf=VBUF,hf=-VBUF;
    __syncthreads();

    for(int s=0;s<TT;s++){
        float4 pA,pB;
        if(s+1<TT){pA=*(const float4*)h1p; pB=*(const float4*)(h1p+4);}
        else {pA=pB=make_float4(0.f,0.f,0.f,0.f);}
        h1p+=2048;

        u64 acc[8][4];
#pragma unroll
        for(int q=0;q<8;q++){u64 bp=pkss(bias[q]);
            acc[q][0]=bp;acc[q][1]=bp;acc[q][2]=bp;acc[q][3]=bp;}

        float p0,p1,p2,p3,q0,q1,q2,q3;
        uint32_t xb=xrd, wb=wb0;
        WLOADP(0);
#pragma unroll 4
        for(int kc=0;kc<16;kc++) PCHUNK;

        if(st==0){ PST(4,pst_a); } else { PST(0,pst_a); }
        STS4(ps,0,pA); STS4(ps,16,pB);
        __syncthreads();                            // partials visible
        if(st==0){ PLA(0,pld_a); UPD8(0); }
        else     { PLA(4,pld_a); UPD8(4); }
        {
            float4 h4=make_float4(hv[0],hv[1],hv[2],hv[3]);
            float4 h5=make_float4(hv[4],hv[5],hv[6],hv[7]);
            STS4(hs,0,h4); STS4(hs,16,h5);
        }
        __syncthreads();                            // v[next] complete
        xrd+=xf;xf=-xf; hs+=hf;ps+=hf;hf=-hf;
    }

    // fused FC: thread owns unit j=2gg+st
    {
        float wf=Wfc[2*gg+st];
        float4 t0=make_float4(hv[0]*wf,hv[1]*wf,hv[2]*wf,hv[3]*wf);
        float4 t1=make_float4(hv[4]*wf,hv[5]*wf,hv[6]*wf,hv[7]*wf);
        uint32_t pb=smb+V_OFF+(2*gg+st)*128+eg*32;
        STS4(pb,0,t0); STS4(pb,16,t1);
        __syncthreads();
        if(tid<32){
            float v=bfc[0];
#pragma unroll
            for(int g=0;g<64;g++) v+=*(const float*)(sm+V_OFF+g*128+tid*4);
            out[b0+tid]=v;
        }
    }
}

// ---------------------------------------------------------------------------
// Layer 0: v rows 0..3 = x (chunk 0), rows 4..67 = h (chunks 1..16).
// Set A: chunks 0..8 (9), set B: chunks 9..16 (8).
__global__ void __launch_bounds__(256,1) lstm_l0(
    const float* __restrict__ x,const float* __restrict__ Wih,
    const float* __restrict__ Whh,const float* __restrict__ bih,
    const float* __restrict__ bhh)
{
    extern __shared__ char sm[];
    const int tid=threadIdx.x, st=tid>>7, t=tid&127, eg=t&3, gg=t>>2;
    const int b0=blockIdx.x*32;

    for(int idx=tid;idx<4352;idx+=256){            // weights [kc17][s8][gg32]
        int kc=idx>>8,s=(idx>>5)&7,g=idx&31;
        int r=(s&3)*64+2*g+(s>>2);
        const float* src = (kc==0)? Wih+r*4 : Whh+r*64+(kc-1)*4;
        *(float4*)(sm+kc*4096+s*512+g*16)=*(const float4*)src;
    }

    const uint32_t smb=s2u(sm);
    const uint32_t wb0=smb+gg*16+st*36864;          // set B starts chunk 9
    uint32_t xrd=smb+V_OFF+eg*32+st*4608;           // set B rows 36..67
    uint32_t hs=smb+V_OFF+VBUF+(4+2*gg+st)*128+eg*32;
    uint32_t xs=smb+V_OFF+VBUF+(tid&127)*4;         // only tid<32 uses
    const uint32_t pst_a=smb+P_OFF+st*16384+t*16;
    const uint32_t pld_a=smb+P_OFF+(1-st)*16384+t*16;
    const int nch = 9 - st;

    {   // V0: h row (4+2gg+st) <- 0
        float4 z=make_float4(0.f,0.f,0.f,0.f);
        uint32_t vi=smb+V_OFF+(4+2*gg+st)*128+eg*32;
        STS4(vi,0,z); STS4(vi,16,z);
    }
    const float* xp=0;
    if(tid<32){
        xp=x+(size_t)(b0+tid)*TT*4;
        float4 x0=*(const float4*)xp;
        uint32_t xi=smb+V_OFF+tid*4;
        STS1(xi,0,x0.x);STS1(xi,128,x0.y);STS1(xi,256,x0.z);STS1(xi,384,x0.w);
    }
    float* gp=g_h1+(size_t)blockIdx.x*TT*2048+(2*gg+st)*32+eg*8;

    float bias[8];
#pragma unroll
    for(int s=0;s<8;s++){
        int r=(s&3)*64+2*gg+(s>>2);
        bias[s]=(st==0)? (bih[r]+bhh[r]) : 0.f;
    }
    float cc[8], hv[8];
#pragma unroll
    for(int e=0;e<8;e++)cc[e]=0.f;
    int xf=VBUF,hf=-VBUF;
    __syncthreads();

    for(int s=0;s<TT;s++){
        float4 px=make_float4(0.f,0.f,0.f,0.f);
        if(tid<32&&s+1<TT)px=*(const float4*)(xp+(size_t)(s+1)*4);

        u64 acc[8][4];
#pragma unroll
        for(int q=0;q<8;q++){u64 bp=pkss(bias[q]);
            acc[q][0]=bp;acc[q][1]=bp;acc[q][2]=bp;acc[q][3]=bp;}

        float p0,p1,p2,p3,q0,q1,q2,q3;
        uint32_t xb=xrd, wb=wb0;
        WLOADP(0);
#pragma unroll 3
        for(int kc=0;kc<nch;kc++) PCHUNK;

        if(st==0){ PST(4,pst_a); } else { PST(0,pst_a); }
        if(tid<32){STS1(xs,0,px.x);STS1(xs,128,px.y);STS1(xs,256,px.z);STS1(xs,384,px.w);}
        __syncthreads();
        if(st==0){ PLA(0,pld_a); UPD8(0); }
        else     { PLA(4,pld_a); UPD8(4); }
        {
            float4 h4=make_float4(hv[0],hv[1],hv[2],hv[3]);
            float4 h5=make_float4(hv[4],hv[5],hv[6],hv[7]);
            STS4(hs,0,h4); STS4(hs,16,h5);
            *(float4*)(gp)  =h4;
            *(float4*)(gp+4)=h5;
        }
        gp+=2048;
        __syncthreads();
        xrd+=xf;xf=-xf; hs+=hf;xs+=hf;hf=-hf;
    }
}

// ---------------------------------------------------------------------------
extern "C" void kernel_launch(void* const* d_in, const int* in_sizes, int n_in,
                              void* d_out, int out_size)
{
    const float* x    =(const float*)d_in[0];
    const float* Wih0 =(const float*)d_in[1];
    const float* Whh0 =(const float*)d_in[2];
    const float* bih0 =(const float*)d_in[3];
    const float* bhh0 =(const float*)d_in[4];
    const float* Wih1 =(const float*)d_in[5];
    const float* Whh1 =(const float*)d_in[6];
    const float* bih1 =(const float*)d_in[7];
    const float* bhh1 =(const float*)d_in[8];
    const float* Wfc  =(const float*)d_in[9];
    const float* bfc  =(const float*)d_in[10];
    float* out=(float*)d_out;

    cudaFuncSetAttribute(lstm_l0,cudaFuncAttributeMaxDynamicSharedMemorySize,SM_TOTAL);
    cudaFuncSetAttribute(lstm_l1,cudaFuncAttributeMaxDynamicSharedMemorySize,SM_TOTAL);
    lstm_l0<<<128,256,SM_TOTAL>>>(x,Wih0,Whh0,bih0,bhh0);
    lstm_l1<<<128,256,SM_TOTAL>>>(Wih1,Whh1,bih1,bhh1,Wfc,bfc,out);
}

// round 14
// speedup vs baseline: 2.3618x; 2.2320x over previous
#include <cuda_runtime.h>
#include <cuda_bf16.h>
#include <cstdint>

// 2-layer LSTM (B=4096,T=256,D=4,H=64)+FC via mma.sync.m16n8k16 bf16
// (fallback HMMA; tcgen05 blocked by non-'a' ptxas target).
// W hi/lo bf16 in swizzled smem (gate-permuted rows so update is in-register),
// V [e32][k] hi/lo double-buffered, 3-pass MMA (hh,hl,lh), fp32 accum,
// bias in C-init, 1 barrier/step, fused FC.

#define TT 256
#define WLO_ 65536
#define VB_  131072
#define BO_  163840
#define SMT_ 164864

typedef unsigned int u32;
__device__ __nv_bfloat16 g_hh[(size_t)128*TT*32*64];
__device__ __nv_bfloat16 g_hl[(size_t)128*TT*32*64];

static __device__ __forceinline__ u32 s2u(const void*p){u32 a;
  asm("{.reg .u64 t;cvta.to.shared.u64 t,%1;cvt.u32.u64 %0,t;}":"=r"(a):"l"(p));return a;}
static __device__ __forceinline__ float tanha(float x){float r;asm("tanh.approx.f32 %0,%1;":"=f"(r):"f"(x));return r;}
static __device__ __forceinline__ float sigt(float x){return fmaf(0.5f,tanha(0.5f*x),0.5f);}
static __device__ __forceinline__ void bsplit(float v,unsigned short&h,unsigned short&l){
  __nv_bfloat16 bh=__float2bfloat16(v); float fh=__bfloat162float(bh);
  __nv_bfloat16 bl=__float2bfloat16(v-fh);
  h=*(unsigned short*)&bh; l=*(unsigned short*)&bl;}

#define LDSM4(D,A) asm volatile("ldmatrix.sync.aligned.m8n8.x4.shared.b16 {%0,%1,%2,%3},[%4];" \
  :"=r"((D)[0]),"=r"((D)[1]),"=r"((D)[2]),"=r"((D)[3]):"r"(A))
#define LDSM2(D,A) asm volatile("ldmatrix.sync.aligned.m8n8.x2.shared.b16 {%0,%1},[%2];" \
  :"=r"((D)[0]),"=r"((D)[1]):"r"(A))
#define MMAB(C,A,B) asm volatile("mma.sync.aligned.m16n8k16.row.col.f32.bf16.bf16.f32 " \
  "{%0,%1,%2,%3},{%4,%5,%6,%7},{%8,%9},{%0,%1,%2,%3};" \
  :"+f"((C)[0]),"+f"((C)[1]),"+f"((C)[2]),"+f"((C)[3]) \
  :"r"((A)[0]),"r"((A)[1]),"r"((A)[2]),"r"((A)[3]),"r"((B)[0]),"r"((B)[1]))
#define STB16(A,V) asm volatile("st.shared.b16 [%0],%1;"::"r"(A),"h"(V))

// smem W row rr <-> logical gate row R: rr = w*64 + gate*16 + (u%16), w=u/16,
// R = gate*64 + u. Swizzle: 16B granule g=k>>3 stored at g^(row&7).
template<int KT,int DIN,int LAYER>
__global__ void __launch_bounds__(128,1) lstm_mma(
  const float* __restrict__ x,const float* __restrict__ Wih,
  const float* __restrict__ Whh,const float* __restrict__ bih,
  const float* __restrict__ bhh,const float* __restrict__ Wfc,
  const float* __restrict__ bfc,float* __restrict__ out)
{
  extern __shared__ char sm[];
  const int tid=threadIdx.x,w=tid>>5,l=tid&31,blk=blockIdx.x;
  const u32 smb=s2u(sm);

  for(int i=tid;i<32768;i+=128){
    int rr=i>>7,k=i&127;
    int wg=rr>>6,gate=(rr>>4)&3,R=gate*64+wg*16+(rr&15);
    float v=0.f;
    if(k<64)v=Whh[R*64+k]; else if(k-64<DIN)v=Wih[R*DIN+k-64];
    unsigned short hh,ll; bsplit(v,hh,ll);
    u32 off=(u32)(rr*256+(((k>>3)^(rr&7))<<4)+((k&7)*2));
    *(unsigned short*)(sm+off)=hh;
    *(unsigned short*)(sm+WLO_+off)=ll;
  }
  for(int i=tid;i<256;i+=128){
    int wg=i>>6,gate=(i>>4)&3,R=gate*64+wg*16+(i&15);
    *(float*)(sm+BO_+i*4)=bih[R]+bhh[R];
  }
  for(int i=tid;i<2048;i+=128)((uint4*)(sm+VB_))[i]=make_uint4(0,0,0,0);
  __syncthreads();

  // initial input into buffer 0 (granules 8..15 of V rows)
  const float* xp=0;
  if(LAYER){
    size_t ib=(size_t)(blk*TT)*32;
#pragma unroll
    for(int q=0;q<2;q++){
      int sx=tid*2+q,e=sx>>3,g8=sx&7;
      u32 off=VB_+(u32)(e*256+(((8+g8)^(e&7))<<4));
      *(uint4*)(sm+off)=*(const uint4*)(const void*)(g_hh+(ib+e)*64+g8*8);
      *(uint4*)(sm+off+8192)=*(const uint4*)(const void*)(g_hl+(ib+e)*64+g8*8);
    }
  } else if(tid<32){
    xp=x+(size_t)(blk*32+tid)*TT*4;
    float4 xv=*(const float4*)xp;
    unsigned short a0,a1,b0,b1,c0v,c1v,d0,d1;
    bsplit(xv.x,a0,a1);bsplit(xv.y,b0,b1);bsplit(xv.z,c0v,c1v);bsplit(xv.w,d0,d1);
    u32 off=VB_+(u32)(tid*256+((8^(tid&7))<<4));
    *(uint4*)(sm+off)=make_uint4((u32)a0|((u32)b0<<16),(u32)c0v|((u32)d0<<16),0,0);
    *(uint4*)(sm+off+8192)=make_uint4((u32)a1|((u32)b1<<16),(u32)c1v|((u32)d1<<16),0,0);
  }
  __syncthreads();

  float blo[4],bhi[4];
#pragma unroll
  for(int mt=0;mt<4;mt++){
    blo[mt]=*(float*)(sm+BO_+(w*64+mt*16+(l>>2))*4);
    bhi[mt]=*(float*)(sm+BO_+(w*64+mt*16+(l>>2)+8)*4);
  }
  const int ra=((l>>3)&1)*8+(l&7),gsel=l>>4,tm=l&15;
  u32 arb[4],brb[4];
#pragma unroll
  for(int mt=0;mt<4;mt++)arb[mt]=smb+(u32)((w*64+mt*16+ra)*256);
#pragma unroll
  for(int nt=0;nt<4;nt++)brb[nt]=(u32)((nt*8+(tm&7))*256);
  const int bgs=tm>>3;

  float cst[16],hn[16];
#pragma unroll
  for(int i=0;i<16;i++)cst[i]=0.f;

  u32 cur=VB_,nxt=VB_+16384;
  for(int s=0;s<TT;s++){
    uint4 pf0h,pf0l,pf1h,pf1l; float4 px=make_float4(0,0,0,0);
    if(LAYER){
      if(s+1<TT){
        size_t ib=(size_t)(blk*TT+s+1)*32;
        int s0=tid*2,e0=s0>>3,g0=s0&7,e1=(s0+1)>>3,g1=(s0+1)&7;
        pf0h=*(const uint4*)(const void*)(g_hh+(ib+e0)*64+g0*8);
        pf0l=*(const uint4*)(const void*)(g_hl+(ib+e0)*64+g0*8);
        pf1h=*(const uint4*)(const void*)(g_hh+(ib+e1)*64+g1*8);
        pf1l=*(const uint4*)(const void*)(g_hl+(ib+e1)*64+g1*8);
      }
    } else if(tid<32&&s+1<TT)px=*(const float4*)(xp+(size_t)(s+1)*4);

    float c[4][4][4];
#pragma unroll
    for(int mt=0;mt<4;mt++)
#pragma unroll
      for(int nt=0;nt<4;nt++){
        c[mt][nt][0]=blo[mt];c[mt][nt][1]=blo[mt];
        c[mt][nt][2]=bhi[mt];c[mt][nt][3]=bhi[mt];
      }
#pragma unroll
    for(int kt=0;kt<KT;kt++){
      u32 sa=(u32)(((2*kt+gsel)^(l&7))<<4);
      u32 sb=(u32)(((2*kt+bgs)^(tm&7))<<4);
      u32 ah[4][4],al[4][4],bhf[4][2],blf[4][2];
#pragma unroll
      for(int mt=0;mt<4;mt++)LDSM4(ah[mt],arb[mt]+sa);
#pragma unroll
      for(int nt=0;nt<4;nt++){
        LDSM2(bhf[nt],smb+cur+brb[nt]+sb);
        LDSM2(blf[nt],smb+cur+8192+brb[nt]+sb);
      }
#pragma unroll
      for(int mt=0;mt<4;mt++)
#pragma unroll
        for(int nt=0;nt<4;nt++){MMAB(c[mt][nt],ah[mt],bhf[nt]);MMAB(c[mt][nt],ah[mt],blf[nt]);}
#pragma unroll
      for(int mt=0;mt<4;mt++)LDSM4(al[mt],arb[mt]+WLO_+sa);
#pragma unroll
      for(int mt=0;mt<4;mt++)
#pragma unroll
        for(int nt=0;nt<4;nt++)MMAB(c[mt][nt],al[mt],bhf[nt]);
    }

    // in-register cell update (gates = 4 m-tiles) + h writeback to nxt
#pragma unroll
    for(int ur=0;ur<2;ur++)
#pragma unroll
      for(int nt=0;nt<4;nt++)
#pragma unroll
        for(int ep=0;ep<2;ep++){
          int id=ur*8+nt*2+ep,ix=2*ur+ep;
          float gi=c[0][nt][ix],gf=c[1][nt][ix],gg=c[2][nt][ix],go=c[3][nt][ix];
          cst[id]=sigt(gf)*cst[id]+sigt(gi)*tanha(gg);
          hn[id]=sigt(go)*tanha(cst[id]);
          int ea=nt*8+2*(l&3)+ep;
          u32 off=(u32)(ea*256+(((2*w+ur)^(ea&7))<<4)+((l>>2)*2));
          unsigned short hh,ll;bsplit(hn[id],hh,ll);
          STB16(smb+nxt+off,hh);
          STB16(smb+nxt+8192+off,ll);
        }

    if(LAYER){
      if(s+1<TT){
        int s0=tid*2,e0=s0>>3,g0=s0&7,e1=(s0+1)>>3,g1=(s0+1)&7;
        u32 o0=nxt+(u32)(e0*256+(((8+g0)^(e0&7))<<4));
        u32 o1=nxt+(u32)(e1*256+(((8+g1)^(e1&7))<<4));
        *(uint4*)(sm+o0)=pf0h;*(uint4*)(sm+o0+8192)=pf0l;
        *(uint4*)(sm+o1)=pf1h;*(uint4*)(sm+o1+8192)=pf1l;
      }
    } else if(tid<32&&s+1<TT){
      unsigned short a0,a1,b0,b1,c0v,c1v,d0,d1;
      bsplit(px.x,a0,a1);bsplit(px.y,b0,b1);bsplit(px.z,c0v,c1v);bsplit(px.w,d0,d1);
      u32 off=nxt+(u32)(tid*256+((8^(tid&7))<<4));
      *(uint4*)(sm+off)=make_uint4((u32)a0|((u32)b0<<16),(u32)c0v|((u32)d0<<16),0,0);
      *(uint4*)(sm+off+8192)=make_uint4((u32)a1|((u32)b1<<16),(u32)c1v|((u32)d1<<16),0,0);
    }
    __syncthreads();
    if(!LAYER){   // ship h1(s) hi/lo to global (reads nxt, post-barrier)
      size_t ob=(size_t)(blk*TT+s)*32;
#pragma unroll
      for(int q=0;q<2;q++){
        int sx=tid*2+q,e=sx>>3,gl=sx&7;
        u32 off=nxt+(u32)(e*256+((gl^(e&7))<<4));
        *(uint4*)(void*)(g_hh+(ob+e)*64+gl*8)=*(uint4*)(sm+off);
        *(uint4*)(void*)(g_hl+(ob+e)*64+gl*8)=*(uint4*)(sm+off+8192);
      }
    }
    u32 tpb=cur;cur=nxt;nxt=tpb;
  }

  if(LAYER){ // fused FC on final h (in regs)
    float wA=Wfc[16*w+(l>>2)],wB=Wfc[16*w+(l>>2)+8];
#pragma unroll
    for(int nt=0;nt<4;nt++)
#pragma unroll
      for(int ep=0;ep<2;ep++){
        int ea=nt*8+2*(l&3)+ep;
        float p=hn[nt*2+ep]*wA+hn[8+nt*2+ep]*wB;
        *(float*)(sm+ea*128+(w*8+(l>>2))*4)=p;
      }
    __syncthreads();
    if(tid<32){
      float v=bfc[0];
#pragma unroll
      for(int q=0;q<32;q++)v+=*(float*)(sm+tid*128+q*4);
      out[blk*32+tid]=v;
    }
  }
}

// ---------------------------------------------------------------------------
extern "C" void kernel_launch(void* const* d_in, const int* in_sizes, int n_in,
                              void* d_out, int out_size)
{
  const float* x    =(const float*)d_in[0];
  const float* Wih0 =(const float*)d_in[1];
  const float* Whh0 =(const float*)d_in[2];
  const float* bih0 =(const float*)d_in[3];
  const float* bhh0 =(const float*)d_in[4];
  const float* Wih1 =(const float*)d_in[5];
  const float* Whh1 =(const float*)d_in[6];
  const float* bih1 =(const float*)d_in[7];
  const float* bhh1 =(const float*)d_in[8];
  const float* Wfc  =(const float*)d_in[9];
  const float* bfc  =(const float*)d_in[10];
  float* out=(float*)d_out;

  cudaFuncSetAttribute(lstm_mma<5,4,0>,cudaFuncAttributeMaxDynamicSharedMemorySize,SMT_);
  cudaFuncSetAttribute(lstm_mma<8,64,1>,cudaFuncAttributeMaxDynamicSharedMemorySize,SMT_);
  lstm_mma<5,4,0><<<128,128,SMT_>>>(x,Wih0,Whh0,bih0,bhh0,Wfc,bfc,out);
  lstm_mma<8,64,1><<<128,128,SMT_>>>(x,Wih1,Whh1,bih1,bhh1,Wfc,bfc,out);
}

// round 15
// speedup vs baseline: 2.4775x; 1.0490x over previous
#include <cuda_runtime.h>
#include <cuda_bf16.h>
#include <cstdint>

// 2-layer LSTM (B=4096,T=256,D=4,H=64)+FC via mma.sync.m16n8k16 bf16 hi/lo
// double-split (3 passes, fp32 accum). R15: 256 threads (2 warps/SMSP) —
// warp w owns the 4 gates of units 8w..8w+7 (2 m-tiles), so cell update
// stays in-register while peer warp's HMMAs cover LDSM/MUFU latency.

#define TT 256
#define WLO_ 65536
#define VB_  131072
#define SMT_ 163840

typedef unsigned int u32;
__device__ __nv_bfloat16 g_hh[(size_t)128*TT*32*64];
__device__ __nv_bfloat16 g_hl[(size_t)128*TT*32*64];

static __device__ __forceinline__ u32 s2u(const void*p){u32 a;
  asm("{.reg .u64 t;cvta.to.shared.u64 t,%1;cvt.u32.u64 %0,t;}":"=r"(a):"l"(p));return a;}
static __device__ __forceinline__ float tanha(float x){float r;asm("tanh.approx.f32 %0,%1;":"=f"(r):"f"(x));return r;}
static __device__ __forceinline__ float sigt(float x){return fmaf(0.5f,tanha(0.5f*x),0.5f);}
static __device__ __forceinline__ void bsplit(float v,unsigned short&h,unsigned short&l){
  __nv_bfloat16 bh=__float2bfloat16(v); float fh=__bfloat162float(bh);
  __nv_bfloat16 bl=__float2bfloat16(v-fh);
  h=*(unsigned short*)&bh; l=*(unsigned short*)&bl;}

#define LDSM4(D,A) asm volatile("ldmatrix.sync.aligned.m8n8.x4.shared.b16 {%0,%1,%2,%3},[%4];" \
  :"=r"((D)[0]),"=r"((D)[1]),"=r"((D)[2]),"=r"((D)[3]):"r"(A))
#define LDSM2(D,A) asm volatile("ldmatrix.sync.aligned.m8n8.x2.shared.b16 {%0,%1},[%2];" \
  :"=r"((D)[0]),"=r"((D)[1]):"r"(A))
#define MMAB(C,A,B) asm volatile("mma.sync.aligned.m16n8k16.row.col.f32.bf16.bf16.f32 " \
  "{%0,%1,%2,%3},{%4,%5,%6,%7},{%8,%9},{%0,%1,%2,%3};" \
  :"+f"((C)[0]),"+f"((C)[1]),"+f"((C)[2]),"+f"((C)[3]) \
  :"r"((A)[0]),"r"((A)[1]),"r"((A)[2]),"r"((A)[3]),"r"((B)[0]),"r"((B)[1]))
#define STB16(A,V) asm volatile("st.shared.b16 [%0],%1;"::"r"(A),"h"(V))

// smem W row rr -> logical gate row R: warp w'=rr>>5, rw=rr&31, mt=rw>>4,
// r=rw&15: gate=mt*2+(r>>3), unit=(rr>>5)*8+(r&7), R=gate*64+unit.
// 16B granule g=k>>3 stored at g^(rr&7).
template<int KT,int DIN,int LAYER>
__global__ void __launch_bounds__(256,1) lstm_mma(
  const float* __restrict__ x,const float* __restrict__ Wih,
  const float* __restrict__ Whh,const float* __restrict__ bih,
  const float* __restrict__ bhh,const float* __restrict__ Wfc,
  const float* __restrict__ bfc,float* __restrict__ out)
{
  extern __shared__ char sm[];
  const int tid=threadIdx.x,w=tid>>5,l=tid&31,blk=blockIdx.x;
  const u32 smb=s2u(sm);

  for(int i=tid;i<32768;i+=256){
    int rr=i>>7,k=i&127;
    int rw=rr&31,mt=rw>>4,r=rw&15;
    int R=(mt*2+(r>>3))*64+(rr>>5)*8+(r&7);
    float v=0.f;
    if(k<64)v=Whh[R*64+k]; else if(k-64<DIN)v=Wih[R*DIN+k-64];
    unsigned short hh,ll; bsplit(v,hh,ll);
    u32 off=(u32)(rr*256+(((k>>3)^(rr&7))<<4)+((k&7)*2));
    *(unsigned short*)(sm+off)=hh;
    *(unsigned short*)(sm+WLO_+off)=ll;
  }
  for(int i=tid;i<2048;i+=256)((uint4*)(sm+VB_))[i]=make_uint4(0,0,0,0);
  __syncthreads();

  // initial input into buffer 0 (granules 8..15 of V rows)
  const float* xp=0;
  if(LAYER){
    if(tid<128){
      size_t ib=(size_t)(blk*TT)*32;
#pragma unroll
      for(int q=0;q<2;q++){
        int sx=tid*2+q,e=sx>>3,g8=sx&7;
        u32 off=VB_+(u32)(e*256+(((8+g8)^(e&7))<<4));
        *(uint4*)(sm+off)=*(const uint4*)(const void*)(g_hh+(ib+e)*64+g8*8);
        *(uint4*)(sm+off+8192)=*(const uint4*)(const void*)(g_hl+(ib+e)*64+g8*8);
      }
    }
  } else if(tid<32){
    xp=x+(size_t)(blk*32+tid)*TT*4;
    float4 xv=*(const float4*)xp;
    unsigned short a0,a1,b0,b1,c0v,c1v,d0,d1;
    bsplit(xv.x,a0,a1);bsplit(xv.y,b0,b1);bsplit(xv.z,c0v,c1v);bsplit(xv.w,d0,d1);
    u32 off=VB_+(u32)(tid*256+((8^(tid&7))<<4));
    *(uint4*)(sm+off)=make_uint4((u32)a0|((u32)b0<<16),(u32)c0v|((u32)d0<<16),0,0);
    *(uint4*)(sm+off+8192)=make_uint4((u32)a1|((u32)b1<<16),(u32)c1v|((u32)d1<<16),0,0);
  }
  __syncthreads();

  // bias per thread: unit u = w*8+(l>>2); blo[mt]=gate 2mt, bhi[mt]=gate 2mt+1
  const int unit=w*8+(l>>2);
  float blo[2],bhi[2];
#pragma unroll
  for(int mt=0;mt<2;mt++){
    blo[mt]=bih[(2*mt)*64+unit]+bhh[(2*mt)*64+unit];
    bhi[mt]=bih[(2*mt+1)*64+unit]+bhh[(2*mt+1)*64+unit];
  }
  const int ra=((l>>3)&1)*8+(l&7),gsel=l>>4,tm=l&15;
  u32 arb[2],brb[4];
#pragma unroll
  for(int mt=0;mt<2;mt++)arb[mt]=smb+(u32)((w*32+mt*16+ra)*256);
#pragma unroll
  for(int nt=0;nt<4;nt++)brb[nt]=(u32)((nt*8+(tm&7))*256);
  const int bgs=tm>>3;

  float cst[8],hn[8];
#pragma unroll
  for(int i=0;i<8;i++)cst[i]=0.f;

  u32 cur=VB_,nxt=VB_+16384;
  for(int s=0;s<TT;s++){
    uint4 pf0h,pf0l,pf1h,pf1l; float4 px=make_float4(0,0,0,0);
    if(LAYER){
      if(tid<128&&s+1<TT){
        size_t ib=(size_t)(blk*TT+s+1)*32;
        int s0=tid*2,e0=s0>>3,g0=s0&7,e1=(s0+1)>>3,g1=(s0+1)&7;
        pf0h=*(const uint4*)(const void*)(g_hh+(ib+e0)*64+g0*8);
        pf0l=*(const uint4*)(const void*)(g_hl+(ib+e0)*64+g0*8);
        pf1h=*(const uint4*)(const void*)(g_hh+(ib+e1)*64+g1*8);
        pf1l=*(const uint4*)(const void*)(g_hl+(ib+e1)*64+g1*8);
      }
    } else if(tid<32&&s+1<TT)px=*(const float4*)(xp+(size_t)(s+1)*4);

    float c[2][4][4];
#pragma unroll
    for(int mt=0;mt<2;mt++)
#pragma unroll
      for(int nt=0;nt<4;nt++){
        c[mt][nt][0]=blo[mt];c[mt][nt][1]=blo[mt];
        c[mt][nt][2]=bhi[mt];c[mt][nt][3]=bhi[mt];
      }
#pragma unroll
    for(int kt=0;kt<KT;kt++){
      u32 sa=(u32)(((2*kt+gsel)^(l&7))<<4);
      u32 sb=(u32)(((2*kt+bgs)^(tm&7))<<4);
      u32 ah[2][4],al[2][4],bhf[4][2],blf[4][2];
#pragma unroll
      for(int mt=0;mt<2;mt++)LDSM4(ah[mt],arb[mt]+sa);
#pragma unroll
      for(int nt=0;nt<4;nt++){
        LDSM2(bhf[nt],smb+cur+brb[nt]+sb);
        LDSM2(blf[nt],smb+cur+8192+brb[nt]+sb);
      }
#pragma unroll
      for(int mt=0;mt<2;mt++)
#pragma unroll
        for(int nt=0;nt<4;nt++){MMAB(c[mt][nt],ah[mt],bhf[nt]);MMAB(c[mt][nt],ah[mt],blf[nt]);}
#pragma unroll
      for(int mt=0;mt<2;mt++)LDSM4(al[mt],arb[mt]+WLO_+sa);
#pragma unroll
      for(int mt=0;mt<2;mt++)
#pragma unroll
        for(int nt=0;nt<4;nt++)MMAB(c[mt][nt],al[mt],bhf[nt]);
    }

    // in-register update: mt0 rows = gates i(lo),f(hi); mt1 = g(lo),o(hi)
#pragma unroll
    for(int nt=0;nt<4;nt++)
#pragma unroll
      for(int ep=0;ep<2;ep++){
        int id=nt*2+ep;
        float gi=c[0][nt][ep],gf=c[0][nt][2+ep];
        float gg=c[1][nt][ep],go=c[1][nt][2+ep];
        cst[id]=sigt(gf)*cst[id]+sigt(gi)*tanha(gg);
        hn[id]=sigt(go)*tanha(cst[id]);
        int ea=nt*8+2*(l&3)+ep;
        u32 off=(u32)(ea*256+((w^(ea&7))<<4)+((l>>2)*2));
        unsigned short hh,ll;bsplit(hn[id],hh,ll);
        STB16(smb+nxt+off,hh);
        STB16(smb+nxt+8192+off,ll);
      }

    if(LAYER){
      if(tid<128&&s+1<TT){
        int s0=tid*2,e0=s0>>3,g0=s0&7,e1=(s0+1)>>3,g1=(s0+1)&7;
        u32 o0=nxt+(u32)(e0*256+(((8+g0)^(e0&7))<<4));
        u32 o1=nxt+(u32)(e1*256+(((8+g1)^(e1&7))<<4));
        *(uint4*)(sm+o0)=pf0h;*(uint4*)(sm+o0+8192)=pf0l;
        *(uint4*)(sm+o1)=pf1h;*(uint4*)(sm+o1+8192)=pf1l;
      }
    } else if(tid<32&&s+1<TT){
      unsigned short a0,a1,b0,b1,c0v,c1v,d0,d1;
      bsplit(px.x,a0,a1);bsplit(px.y,b0,b1);bsplit(px.z,c0v,c1v);bsplit(px.w,d0,d1);
      u32 off=nxt+(u32)(tid*256+((8^(tid&7))<<4));
      *(uint4*)(sm+off)=make_uint4((u32)a0|((u32)b0<<16),(u32)c0v|((u32)d0<<16),0,0);
      *(uint4*)(sm+off+8192)=make_uint4((u32)a1|((u32)b1<<16),(u32)c1v|((u32)d1<<16),0,0);
    }
    __syncthreads();
    if(!LAYER){   // ship h1(s) hi/lo to global (reads nxt, post-barrier)
      if(tid<128){
        size_t ob=(size_t)(blk*TT+s)*32;
#pragma unroll
        for(int q=0;q<2;q++){
          int sx=tid*2+q,e=sx>>3,gl=sx&7;
          u32 off=nxt+(u32)(e*256+((gl^(e&7))<<4));
          *(uint4*)(void*)(g_hh+(ob+e)*64+gl*8)=*(uint4*)(sm+off);
          *(uint4*)(void*)(g_hl+(ob+e)*64+gl*8)=*(uint4*)(sm+off+8192);
        }
      }
    }
    u32 tpb=cur;cur=nxt;nxt=tpb;
  }

  if(LAYER){ // fused FC: thread owns unit; partial per elem -> smem -> reduce
    float wA=Wfc[unit];
    __syncthreads();           // safe reuse of V region
#pragma unroll
    for(int nt=0;nt<4;nt++)
#pragma unroll
      for(int ep=0;ep<2;ep++){
        int ea=nt*8+2*(l&3)+ep;
        *(float*)(sm+VB_+ea*256+unit*4)=hn[nt*2+ep]*wA;
      }
    __syncthreads();
    if(tid<32){
      float v=bfc[0];
#pragma unroll
      for(int q=0;q<64;q++)v+=*(float*)(sm+VB_+tid*256+q*4);
      out[blk*32+tid]=v;
    }
  }
}

// ---------------------------------------------------------------------------
extern "C" void kernel_launch(void* const* d_in, const int* in_sizes, int n_in,
                              void* d_out, int out_size)
{
  const float* x    =(const float*)d_in[0];
  const float* Wih0 =(const float*)d_in[1];
  const float* Whh0 =(const float*)d_in[2];
  const float* bih0 =(const float*)d_in[3];
  const float* bhh0 =(const float*)d_in[4];
  const float* Wih1 =(const float*)d_in[5];
  const float* Whh1 =(const float*)d_in[6];
  const float* bih1 =(const float*)d_in[7];
  const float* bhh1 =(const float*)d_in[8];
  const float* Wfc  =(const float*)d_in[9];
  const float* bfc  =(const float*)d_in[10];
  float* out=(float*)d_out;

  cudaFuncSetAttribute(lstm_mma<5,4,0>,cudaFuncAttributeMaxDynamicSharedMemorySize,SMT_);
  cudaFuncSetAttribute(lstm_mma<8,64,1>,cudaFuncAttributeMaxDynamicSharedMemorySize,SMT_);
  lstm_mma<5,4,0><<<128,256,SMT_>>>(x,Wih0,Whh0,bih0,bhh0,Wfc,bfc,out);
  lstm_mma<8,64,1><<<128,256,SMT_>>>(x,Wih1,Whh1,bih1,bhh1,Wfc,bfc,out);
}

// round 16
// speedup vs baseline: 2.5353x; 1.0234x over previous
#include <cuda_runtime.h>
#include <cuda_bf16.h>
#include <cstdint>

// 2-layer LSTM (B=4096,T=256,D=4,H=64)+FC via mma.sync.m16n8k16 bf16 hi/lo
// double-split (3 passes, fp32 accum). R16: A-hi fragments hoisted into
// registers for the whole time loop (weights step-invariant); B fragments
// via ldmatrix.x4 (2 n-tiles per instr). LDSM per step per warp: 96 -> 48.

#define TT 256
#define WLO_ 65536
#define VB_  131072
#define SMT_ 163840

typedef unsigned int u32;
__device__ __nv_bfloat16 g_hh[(size_t)128*TT*32*64];
__device__ __nv_bfloat16 g_hl[(size_t)128*TT*32*64];

static __device__ __forceinline__ u32 s2u(const void*p){u32 a;
  asm("{.reg .u64 t;cvta.to.shared.u64 t,%1;cvt.u32.u64 %0,t;}":"=r"(a):"l"(p));return a;}
static __device__ __forceinline__ float tanha(float x){float r;asm("tanh.approx.f32 %0,%1;":"=f"(r):"f"(x));return r;}
static __device__ __forceinline__ float sigt(float x){return fmaf(0.5f,tanha(0.5f*x),0.5f);}
static __device__ __forceinline__ void bsplit(float v,unsigned short&h,unsigned short&l){
  __nv_bfloat16 bh=__float2bfloat16(v); float fh=__bfloat162float(bh);
  __nv_bfloat16 bl=__float2bfloat16(v-fh);
  h=*(unsigned short*)&bh; l=*(unsigned short*)&bl;}

#define LDSM4(D,A) asm volatile("ldmatrix.sync.aligned.m8n8.x4.shared.b16 {%0,%1,%2,%3},[%4];" \
  :"=r"((D)[0]),"=r"((D)[1]),"=r"((D)[2]),"=r"((D)[3]):"r"(A))
#define MMAB(C,A,B) asm volatile("mma.sync.aligned.m16n8k16.row.col.f32.bf16.bf16.f32 " \
  "{%0,%1,%2,%3},{%4,%5,%6,%7},{%8,%9},{%0,%1,%2,%3};" \
  :"+f"((C)[0]),"+f"((C)[1]),"+f"((C)[2]),"+f"((C)[3]) \
  :"r"((A)[0]),"r"((A)[1]),"r"((A)[2]),"r"((A)[3]),"r"((B)[0]),"r"((B)[1]))
#define STB16(A,V) asm volatile("st.shared.b16 [%0],%1;"::"r"(A),"h"(V))

// smem W row rr -> logical gate row R: rw=rr&31, mt=rw>>4, r=rw&15:
// R=(mt*2+(r>>3))*64+(rr>>5)*8+(r&7). 16B granule g=k>>3 stored at g^(rr&7).
template<int KT,int DIN,int LAYER>
__global__ void __launch_bounds__(256,1) lstm_mma(
  const float* __restrict__ x,const float* __restrict__ Wih,
  const float* __restrict__ Whh,const float* __restrict__ bih,
  const float* __restrict__ bhh,const float* __restrict__ Wfc,
  const float* __restrict__ bfc,float* __restrict__ out)
{
  extern __shared__ char sm[];
  const int tid=threadIdx.x,w=tid>>5,l=tid&31,blk=blockIdx.x;
  const u32 smb=s2u(sm);

  for(int i=tid;i<32768;i+=256){
    int rr=i>>7,k=i&127;
    int rw=rr&31,mt=rw>>4,r=rw&15;
    int R=(mt*2+(r>>3))*64+(rr>>5)*8+(r&7);
    float v=0.f;
    if(k<64)v=Whh[R*64+k]; else if(k-64<DIN)v=Wih[R*DIN+k-64];
    unsigned short hh,ll; bsplit(v,hh,ll);
    u32 off=(u32)(rr*256+(((k>>3)^(rr&7))<<4)+((k&7)*2));
    *(unsigned short*)(sm+off)=hh;
    *(unsigned short*)(sm+WLO_+off)=ll;
  }
  for(int i=tid;i<2048;i+=256)((uint4*)(sm+VB_))[i]=make_uint4(0,0,0,0);
  __syncthreads();

  // A addressing (lane roles) + hoist A-hi fragments for all KT k-tiles
  const int ra=((l>>3)&1)*8+(l&7),gsel=l>>4;
  u32 arb[2];
#pragma unroll
  for(int mt=0;mt<2;mt++)arb[mt]=smb+(u32)((w*32+mt*16+ra)*256);
  u32 ahr[2][KT][4];
#pragma unroll
  for(int kt=0;kt<KT;kt++){
    u32 sa=(u32)(((2*kt+gsel)^(l&7))<<4);
    LDSM4(ahr[0][kt],arb[0]+sa);
    LDSM4(ahr[1][kt],arb[1]+sa);
  }

  // B lane roles for ldmatrix.x4: matrix m=l>>3 -> (nt parity m>>1, k-half m&1)
  const int m_=l>>3, er=l&7, pb=m_&1;
  u32 bb[2]; int se[2];
#pragma unroll
  for(int j=0;j<2;j++){ int e=16*j+(m_>>1)*8+er; bb[j]=(u32)(e*256); se[j]=e&7; }

  // initial input into buffer 0 (granules 8..15 of V rows)
  const float* xp=0;
  if(LAYER){
    if(tid<128){
      size_t ib=(size_t)(blk*TT)*32;
#pragma unroll
      for(int q=0;q<2;q++){
        int sx=tid*2+q,e=sx>>3,g8=sx&7;
        u32 off=VB_+(u32)(e*256+(((8+g8)^(e&7))<<4));
        *(uint4*)(sm+off)=*(const uint4*)(const void*)(g_hh+(ib+e)*64+g8*8);
        *(uint4*)(sm+off+8192)=*(const uint4*)(const void*)(g_hl+(ib+e)*64+g8*8);
      }
    }
  } else if(tid<32){
    xp=x+(size_t)(blk*32+tid)*TT*4;
    float4 xv=*(const float4*)xp;
    unsigned short a0,a1,b0,b1,c0v,c1v,d0,d1;
    bsplit(xv.x,a0,a1);bsplit(xv.y,b0,b1);bsplit(xv.z,c0v,c1v);bsplit(xv.w,d0,d1);
    u32 off=VB_+(u32)(tid*256+((8^(tid&7))<<4));
    *(uint4*)(sm+off)=make_uint4((u32)a0|((u32)b0<<16),(u32)c0v|((u32)d0<<16),0,0);
    *(uint4*)(sm+off+8192)=make_uint4((u32)a1|((u32)b1<<16),(u32)c1v|((u32)d1<<16),0,0);
  }
  __syncthreads();

  const int unit=w*8+(l>>2);
  float blo[2],bhi[2];
#pragma unroll
  for(int mt=0;mt<2;mt++){
    blo[mt]=bih[(2*mt)*64+unit]+bhh[(2*mt)*64+unit];
    bhi[mt]=bih[(2*mt+1)*64+unit]+bhh[(2*mt+1)*64+unit];
  }

  float cst[8],hn[8];
#pragma unroll
  for(int i=0;i<8;i++)cst[i]=0.f;

  u32 cur=VB_,nxt=VB_+16384;
  for(int s=0;s<TT;s++){
    uint4 pf0h,pf0l,pf1h,pf1l; float4 px=make_float4(0,0,0,0);
    if(LAYER){
      if(tid<128&&s+1<TT){
        size_t ib=(size_t)(blk*TT+s+1)*32;
        int s0=tid*2,e0=s0>>3,g0=s0&7,e1=(s0+1)>>3,g1=(s0+1)&7;
        pf0h=*(const uint4*)(const void*)(g_hh+(ib+e0)*64+g0*8);
        pf0l=*(const uint4*)(const void*)(g_hl+(ib+e0)*64+g0*8);
        pf1h=*(const uint4*)(const void*)(g_hh+(ib+e1)*64+g1*8);
        pf1l=*(const uint4*)(const void*)(g_hl+(ib+e1)*64+g1*8);
      }
    } else if(tid<32&&s+1<TT)px=*(const float4*)(xp+(size_t)(s+1)*4);

    float c[2][4][4];
#pragma unroll
    for(int mt=0;mt<2;mt++)
#pragma unroll
      for(int nt=0;nt<4;nt++){
        c[mt][nt][0]=blo[mt];c[mt][nt][1]=blo[mt];
        c[mt][nt][2]=bhi[mt];c[mt][nt][3]=bhi[mt];
      }
#pragma unroll
    for(int kt=0;kt<KT;kt++){
      u32 g0=(u32)((((kt<<1)|pb)^se[0])<<4);
      u32 g1=(u32)((((kt<<1)|pb)^se[1])<<4);
      u32 bh0[4],bh1[4],bl0[4],bl1[4],al0[4],al1[4];
      LDSM4(bh0,smb+cur+bb[0]+g0);
      LDSM4(bh1,smb+cur+bb[1]+g1);
      LDSM4(bl0,smb+cur+8192+bb[0]+g0);
      LDSM4(bl1,smb+cur+8192+bb[1]+g1);
      u32 sa=(u32)(((2*kt+gsel)^(l&7))<<4);
      LDSM4(al0,arb[0]+WLO_+sa);
      LDSM4(al1,arb[1]+WLO_+sa);
      // pass hh
      MMAB(c[0][0],ahr[0][kt],bh0);   MMAB(c[0][1],ahr[0][kt],bh0+2);
      MMAB(c[0][2],ahr[0][kt],bh1);   MMAB(c[0][3],ahr[0][kt],bh1+2);
      MMAB(c[1][0],ahr[1][kt],bh0);   MMAB(c[1][1],ahr[1][kt],bh0+2);
      MMAB(c[1][2],ahr[1][kt],bh1);   MMAB(c[1][3],ahr[1][kt],bh1+2);
      // pass hl (A-hi x V-lo)
      MMAB(c[0][0],ahr[0][kt],bl0);   MMAB(c[0][1],ahr[0][kt],bl0+2);
      MMAB(c[0][2],ahr[0][kt],bl1);   MMAB(c[0][3],ahr[0][kt],bl1+2);
      MMAB(c[1][0],ahr[1][kt],bl0);   MMAB(c[1][1],ahr[1][kt],bl0+2);
      MMAB(c[1][2],ahr[1][kt],bl1);   MMAB(c[1][3],ahr[1][kt],bl1+2);
      // pass lh (A-lo x V-hi)
      MMAB(c[0][0],al0,bh0);          MMAB(c[0][1],al0,bh0+2);
      MMAB(c[0][2],al0,bh1);          MMAB(c[0][3],al0,bh1+2);
      MMAB(c[1][0],al1,bh0);          MMAB(c[1][1],al1,bh0+2);
      MMAB(c[1][2],al1,bh1);          MMAB(c[1][3],al1,bh1+2);
    }

    // in-register update: mt0 rows = gates i(lo),f(hi); mt1 = g(lo),o(hi)
#pragma unroll
    for(int nt=0;nt<4;nt++)
#pragma unroll
      for(int ep=0;ep<2;ep++){
        int id=nt*2+ep;
        float gi=c[0][nt][ep],gf=c[0][nt][2+ep];
        float gg=c[1][nt][ep],go=c[1][nt][2+ep];
        cst[id]=sigt(gf)*cst[id]+sigt(gi)*tanha(gg);
        hn[id]=sigt(go)*tanha(cst[id]);
        int ea=nt*8+2*(l&3)+ep;
        u32 off=(u32)(ea*256+((w^(ea&7))<<4)+((l>>2)*2));
        unsigned short hh,ll;bsplit(hn[id],hh,ll);
        STB16(smb+nxt+off,hh);
        STB16(smb+nxt+8192+off,ll);
      }

    if(LAYER){
      if(tid<128&&s+1<TT){
        int s0=tid*2,e0=s0>>3,g0=s0&7,e1=(s0+1)>>3,g1=(s0+1)&7;
        u32 o0=nxt+(u32)(e0*256+(((8+g0)^(e0&7))<<4));
        u32 o1=nxt+(u32)(e1*256+(((8+g1)^(e1&7))<<4));
        *(uint4*)(sm+o0)=pf0h;*(uint4*)(sm+o0+8192)=pf0l;
        *(uint4*)(sm+o1)=pf1h;*(uint4*)(sm+o1+8192)=pf1l;
      }
    } else if(tid<32&&s+1<TT){
      unsigned short a0,a1,b0,b1,c0v,c1v,d0,d1;
      bsplit(px.x,a0,a1);bsplit(px.y,b0,b1);bsplit(px.z,c0v,c1v);bsplit(px.w,d0,d1);
      u32 off=nxt+(u32)(tid*256+((8^(tid&7))<<4));
      *(uint4*)(sm+off)=make_uint4((u32)a0|((u32)b0<<16),(u32)c0v|((u32)d0<<16),0,0);
      *(uint4*)(sm+off+8192)=make_uint4((u32)a1|((u32)b1<<16),(u32)c1v|((u32)d1<<16),0,0);
    }
    __syncthreads();
    if(!LAYER){   // ship h1(s) hi/lo to global (reads nxt, post-barrier)
      if(tid<128){
        size_t ob=(size_t)(blk*TT+s)*32;
#pragma unroll
        for(int q=0;q<2;q++){
          int sx=tid*2+q,e=sx>>3,gl=sx&7;
          u32 off=nxt+(u32)(e*256+((gl^(e&7))<<4));
          *(uint4*)(void*)(g_hh+(ob+e)*64+gl*8)=*(uint4*)(sm+off);
          *(uint4*)(void*)(g_hl+(ob+e)*64+gl*8)=*(uint4*)(sm+off+8192);
        }
      }
    }
    u32 tpb=cur;cur=nxt;nxt=tpb;
  }

  if(LAYER){ // fused FC: thread owns unit; partial per elem -> smem -> reduce
    float wA=Wfc[unit];
    __syncthreads();
#pragma unroll
    for(int nt=0;nt<4;nt++)
#pragma unroll
      for(int ep=0;ep<2;ep++){
        int ea=nt*8+2*(l&3)+ep;
        *(float*)(sm+VB_+ea*256+unit*4)=hn[nt*2+ep]*wA;
      }
    __syncthreads();
    if(tid<32){
      float v=bfc[0];
#pragma unroll
      for(int q=0;q<64;q++)v+=*(float*)(sm+VB_+tid*256+q*4);
      out[blk*32+tid]=v;
    }
  }
}

// ---------------------------------------------------------------------------
extern "C" void kernel_launch(void* const* d_in, const int* in_sizes, int n_in,
                              void* d_out, int out_size)
{
  const float* x    =(const float*)d_in[0];
  const float* Wih0 =(const float*)d_in[1];
  const float* Whh0 =(const float*)d_in[2];
  const float* bih0 =(const float*)d_in[3];
  const float* bhh0 =(const float*)d_in[4];
  const float* Wih1 =(const float*)d_in[5];
  const float* Whh1 =(const float*)d_in[6];
  const float* bih1 =(const float*)d_in[7];
  const float* bhh1 =(const float*)d_in[8];
  const float* Wfc  =(const float*)d_in[9];
  const float* bfc  =(const float*)d_in[10];
  float* out=(float*)d_out;

  cudaFuncSetAttribute(lstm_mma<5,4,0>,cudaFuncAttributeMaxDynamicSharedMemorySize,SMT_);
  cudaFuncSetAttribute(lstm_mma<8,64,1>,cudaFuncAttributeMaxDynamicSharedMemorySize,SMT_);
  lstm_mma<5,4,0><<<128,256,SMT_>>>(x,Wih0,Whh0,bih0,bhh0,Wfc,bfc,out);
  lstm_mma<8,64,1><<<128,256,SMT_>>>(x,Wih1,Whh1,bih1,bhh1,Wfc,bfc,out);
}

// round 17
// speedup vs baseline: 2.6979x; 1.0641x over previous
#include <cuda_runtime.h>
#include <cuda_bf16.h>
#include <cstdint>

// 2-layer LSTM (B=4096,T=256,D=4,H=64)+FC via mma.sync.m16n8k16 bf16 hi/lo
// double-split (3 passes, fp32 accum). R17: CTA split into TWO independent
// 128-thread groups (16 elems each, own V double-buffer, own named barrier)
// so one group's MMA stream covers the other's update/barrier window.

#define TT 256
#define WLO_ 65536
#define VB_  131072
#define SMT_ 163840

typedef unsigned int u32;
__device__ __nv_bfloat16 g_hh[(size_t)128*TT*32*64];
__device__ __nv_bfloat16 g_hl[(size_t)128*TT*32*64];

static __device__ __forceinline__ u32 s2u(const void*p){u32 a;
  asm("{.reg .u64 t;cvta.to.shared.u64 t,%1;cvt.u32.u64 %0,t;}":"=r"(a):"l"(p));return a;}
static __device__ __forceinline__ float tanha(float x){float r;asm("tanh.approx.f32 %0,%1;":"=f"(r):"f"(x));return r;}
static __device__ __forceinline__ float sigt(float x){return fmaf(0.5f,tanha(0.5f*x),0.5f);}
static __device__ __forceinline__ void bsplit(float v,unsigned short&h,unsigned short&l){
  __nv_bfloat16 bh=__float2bfloat16(v); float fh=__bfloat162float(bh);
  __nv_bfloat16 bl=__float2bfloat16(v-fh);
  h=*(unsigned short*)&bh; l=*(unsigned short*)&bl;}

#define LDSM4(D,A) asm volatile("ldmatrix.sync.aligned.m8n8.x4.shared.b16 {%0,%1,%2,%3},[%4];" \
  :"=r"((D)[0]),"=r"((D)[1]),"=r"((D)[2]),"=r"((D)[3]):"r"(A))
#define MMAB(C,A,B) asm volatile("mma.sync.aligned.m16n8k16.row.col.f32.bf16.bf16.f32 " \
  "{%0,%1,%2,%3},{%4,%5,%6,%7},{%8,%9},{%0,%1,%2,%3};" \
  :"+f"((C)[0]),"+f"((C)[1]),"+f"((C)[2]),"+f"((C)[3]) \
  :"r"((A)[0]),"r"((A)[1]),"r"((A)[2]),"r"((A)[3]),"r"((B)[0]),"r"((B)[1]))
#define STB16(A,V) asm volatile("st.shared.b16 [%0],%1;"::"r"(A),"h"(V))
#define GBAR(ID) asm volatile("bar.sync %0,%1;"::"r"(ID),"r"(128):"memory")

// smem W row rr -> logical gate row R: wg=rr>>6, gate=(rr>>4)&3, r=rr&15:
// R = gate*64 + wg*16 + r. 16B granule gidx=k>>3 stored at gidx^(rr&7).
template<int KT,int DIN,int LAYER>
__global__ void __launch_bounds__(256,1) lstm_mma(
  const float* __restrict__ x,const float* __restrict__ Wih,
  const float* __restrict__ Whh,const float* __restrict__ bih,
  const float* __restrict__ bhh,const float* __restrict__ Wfc,
  const float* __restrict__ bfc,float* __restrict__ out)
{
  extern __shared__ char sm[];
  const int tid=threadIdx.x,w=tid>>5,l=tid&31,blk=blockIdx.x;
  const int g=w>>2, wg=w&3, lt=tid&127;
  const u32 smb=s2u(sm);

  for(int i=tid;i<32768;i+=256){
    int rr=i>>7,k=i&127;
    int R=((rr>>4)&3)*64+(rr>>6)*16+(rr&15);
    float v=0.f;
    if(k<64)v=Whh[R*64+k]; else if(k-64<DIN)v=Wih[R*DIN+k-64];
    unsigned short hh,ll; bsplit(v,hh,ll);
    u32 off=(u32)(rr*256+(((k>>3)^(rr&7))<<4)+((k&7)*2));
    *(unsigned short*)(sm+off)=hh;
    *(unsigned short*)(sm+WLO_+off)=ll;
  }
  for(int i=tid;i<2048;i+=256)((uint4*)(sm+VB_))[i]=make_uint4(0,0,0,0);
  __syncthreads();

  // A lane roles (warp wg owns gates of units wg*16..wg*16+15; m-tile = gate)
  const int ra=((l>>3)&1)*8+(l&7),gsel=l>>4;
  u32 arb[4];
#pragma unroll
  for(int mt=0;mt<4;mt++)arb[mt]=smb+(u32)((wg*64+mt*16+ra)*256);

  // B lane roles for ldmatrix.x4 (one x4 = both n-tiles, both k-granules)
  const int m_=l>>3, eloc=((m_>>1)&1)*8+(l&7), pb=m_&1;
  const u32 eb=(u32)(eloc*256); const int se=eloc&7;

  // group V double-buffer (offsets within sm)
  u32 curo=VB_+(u32)(g*16384), nxto=curo+8192;

  // initial input into group's buffer 0 (granules 8..15)
  const float* xp=0;
  if(LAYER){
    size_t ib=(size_t)(blk*TT)*32;
    int e=lt>>3,g8=lt&7,E=g*16+e;
    u32 off=curo+(u32)(e*256+(((8+g8)^(e&7))<<4));
    *(uint4*)(sm+off)=*(const uint4*)(const void*)(g_hh+(ib+E)*64+g8*8);
    *(uint4*)(sm+off+4096)=*(const uint4*)(const void*)(g_hl+(ib+E)*64+g8*8);
  } else if(lt<16){
    xp=x+(size_t)(blk*32+g*16+lt)*TT*4;
    float4 xv=*(const float4*)xp;
    unsigned short a0,a1,b0,b1,c0v,c1v,d0,d1;
    bsplit(xv.x,a0,a1);bsplit(xv.y,b0,b1);bsplit(xv.z,c0v,c1v);bsplit(xv.w,d0,d1);
    u32 off=curo+(u32)(lt*256+((8^(lt&7))<<4));
    *(uint4*)(sm+off)=make_uint4((u32)a0|((u32)b0<<16),(u32)c0v|((u32)d0<<16),0,0);
    *(uint4*)(sm+off+4096)=make_uint4((u32)a1|((u32)b1<<16),(u32)c1v|((u32)d1<<16),0,0);
  }
  __syncthreads();

  // bias: thread's units u0=wg*16+(l>>2), u0+8; per gate mt
  const int u0=wg*16+(l>>2);
  float blo[4],bhi[4];
#pragma unroll
  for(int mt=0;mt<4;mt++){
    blo[mt]=bih[mt*64+u0]+bhh[mt*64+u0];
    bhi[mt]=bih[mt*64+u0+8]+bhh[mt*64+u0+8];
  }

  float cst[8],hn[8];
#pragma unroll
  for(int i=0;i<8;i++)cst[i]=0.f;
  const int barid=1+g;

  for(int s=0;s<TT;s++){
    uint4 pfh,pfl; float4 px=make_float4(0,0,0,0);
    if(LAYER){
      if(s+1<TT){
        size_t ib=(size_t)(blk*TT+s+1)*32;
        int e=lt>>3,g8=lt&7,E=g*16+e;
        pfh=*(const uint4*)(const void*)(g_hh+(ib+E)*64+g8*8);
        pfl=*(const uint4*)(const void*)(g_hl+(ib+E)*64+g8*8);
      }
    } else if(lt<16&&s+1<TT)px=*(const float4*)(xp+(size_t)(s+1)*4);

    float c[4][2][4];
#pragma unroll
    for(int mt=0;mt<4;mt++)
#pragma unroll
      for(int nt=0;nt<2;nt++){
        c[mt][nt][0]=blo[mt];c[mt][nt][1]=blo[mt];
        c[mt][nt][2]=bhi[mt];c[mt][nt][3]=bhi[mt];
      }
#pragma unroll
    for(int kt=0;kt<KT;kt++){
      u32 gb=(u32)((((kt<<1)|pb)^se)<<4);
      u32 sa=(u32)(((2*kt+gsel)^(l&7))<<4);
      u32 bh[4],bl[4];
      LDSM4(bh,smb+curo+eb+gb);
      LDSM4(bl,smb+curo+4096+eb+gb);
#pragma unroll
      for(int mt=0;mt<4;mt++){
        u32 ah[4];
        LDSM4(ah,arb[mt]+sa);
        MMAB(c[mt][0],ah,bh);   MMAB(c[mt][1],ah,bh+2);
        MMAB(c[mt][0],ah,bl);   MMAB(c[mt][1],ah,bl+2);
      }
#pragma unroll
      for(int mt=0;mt<4;mt++){
        u32 al[4];
        LDSM4(al,arb[mt]+WLO_+sa);
        MMAB(c[mt][0],al,bh);   MMAB(c[mt][1],al,bh+2);
      }
    }

    // in-register update: gate = m-tile; rows l>>2 (ur=0) and +8 (ur=1)
#pragma unroll
    for(int ur=0;ur<2;ur++)
#pragma unroll
      for(int nt=0;nt<2;nt++)
#pragma unroll
        for(int ep=0;ep<2;ep++){
          int id=ur*4+nt*2+ep, ix=2*ur+ep;
          float gi=c[0][nt][ix],gf=c[1][nt][ix],gg=c[2][nt][ix],go=c[3][nt][ix];
          cst[id]=sigt(gf)*cst[id]+sigt(gi)*tanha(gg);
          hn[id]=sigt(go)*tanha(cst[id]);
          int ea=nt*8+2*(l&3)+ep;
          u32 off=(u32)(ea*256+(((wg*2+ur)^(ea&7))<<4)+((l>>2)*2));
          unsigned short hh,ll;bsplit(hn[id],hh,ll);
          STB16(smb+nxto+off,hh);
          STB16(smb+nxto+4096+off,ll);
        }

    if(LAYER){
      if(s+1<TT){
        int e=lt>>3,g8=lt&7;
        u32 off=nxto+(u32)(e*256+(((8+g8)^(e&7))<<4));
        *(uint4*)(sm+off)=pfh;*(uint4*)(sm+off+4096)=pfl;
      }
    } else if(lt<16&&s+1<TT){
      unsigned short a0,a1,b0,b1,c0v,c1v,d0,d1;
      bsplit(px.x,a0,a1);bsplit(px.y,b0,b1);bsplit(px.z,c0v,c1v);bsplit(px.w,d0,d1);
      u32 off=nxto+(u32)(lt*256+((8^(lt&7))<<4));
      *(uint4*)(sm+off)=make_uint4((u32)a0|((u32)b0<<16),(u32)c0v|((u32)d0<<16),0,0);
      *(uint4*)(sm+off+4096)=make_uint4((u32)a1|((u32)b1<<16),(u32)c1v|((u32)d1<<16),0,0);
    }
    GBAR(barid);
    if(!LAYER){   // ship h1(s) hi/lo to global (reads group's nxt, post-barrier)
      size_t ob=(size_t)(blk*TT+s)*32;
      int e=lt>>3,g8=lt&7,E=g*16+e;
      u32 off=nxto+(u32)(e*256+((g8^(e&7))<<4));
      *(uint4*)(void*)(g_hh+(ob+E)*64+g8*8)=*(uint4*)(sm+off);
      *(uint4*)(void*)(g_hl+(ob+E)*64+g8*8)=*(uint4*)(sm+off+4096);
    }
    u32 tpo=curo;curo=nxto;nxto=tpo;
  }

  if(LAYER){ // fused FC: partials -> smem -> 32-thread reduce
    float wA=Wfc[u0],wB=Wfc[u0+8];
    __syncthreads();
#pragma unroll
    for(int nt=0;nt<2;nt++)
#pragma unroll
      for(int ep=0;ep<2;ep++){
        int ea=g*16+nt*8+2*(l&3)+ep;
        float p=hn[nt*2+ep]*wA+hn[4+nt*2+ep]*wB;
        *(float*)(sm+VB_+ea*128+(wg*8+(l>>2))*4)=p;
      }
    __syncthreads();
    if(tid<32){
      float v=bfc[0];
#pragma unroll
      for(int q=0;q<32;q++)v+=*(float*)(sm+VB_+tid*128+q*4);
      out[blk*32+tid]=v;
    }
  }
}

// ---------------------------------------------------------------------------
extern "C" void kernel_launch(void* const* d_in, const int* in_sizes, int n_in,
                              void* d_out, int out_size)
{
  const float* x    =(const float*)d_in[0];
  const float* Wih0 =(const float*)d_in[1];
  const float* Whh0 =(const float*)d_in[2];
  const float* bih0 =(const float*)d_in[3];
  const float* bhh0 =(const float*)d_in[4];
  const float* Wih1 =(const float*)d_in[5];
  const float* Whh1 =(const float*)d_in[6];
  const float* bih1 =(const float*)d_in[7];
  const float* bhh1 =(const float*)d_in[8];
  const float* Wfc  =(const float*)d_in[9];
  const float* bfc  =(const float*)d_in[10];
  float* out=(float*)d_out;

  cudaFuncSetAttribute(lstm_mma<5,4,0>,cudaFuncAttributeMaxDynamicSharedMemorySize,SMT_);
  cudaFuncSetAttribute(lstm_mma<8,64,1>,cudaFuncAttributeMaxDynamicSharedMemorySize,SMT_);
  lstm_mma<5,4,0><<<128,256,SMT_>>>(x,Wih0,Whh0,bih0,bhh0,Wfc,bfc,out);
  lstm_mma<8,64,1><<<128,256,SMT_>>>(x,Wih1,Whh1,bih1,bhh1,Wfc,bfc,out);
}